// round 1
// baseline (speedup 1.0000x reference)
#include <cuda_runtime.h>
#include <math.h>

#define NB 4096
#define NC 256

// Per-circuit precomputed trig: [c][0..3]=cos(w0/2), [4..7]=sin(w0/2),
//                               [8..11]=cos(w1/2), [12..15]=sin(w1/2)
__device__ float g_wtrig[NC * 16];

__global__ void prep_kernel(const float* __restrict__ w) {
    int c = threadIdx.x;
    if (c >= NC) return;
#pragma unroll
    for (int l = 0; l < 2; ++l) {
#pragma unroll
        for (int q = 0; q < 4; ++q) {
            float a = 0.5f * w[c * 8 + l * 4 + q];
            float s, co;
            sincosf(a, &s, &co);
            g_wtrig[c * 16 + l * 8 + q] = co;
            g_wtrig[c * 16 + l * 8 + 4 + q] = s;
        }
    }
}

// sin(t), cos(t) via Taylor-Horner (|t| <= ~3.2, err < 2e-5): FMA-pipe only.
__device__ __forceinline__ void sincos_poly(float t, float& s, float& c) {
    float u = t * t;
    float ps = 1.6059044e-10f;
    ps = fmaf(ps, u, -2.5052108e-8f);
    ps = fmaf(ps, u, 2.7557319e-6f);
    ps = fmaf(ps, u, -1.9841270e-4f);
    ps = fmaf(ps, u, 8.3333333e-3f);
    ps = fmaf(ps, u, -1.6666667e-1f);
    ps = fmaf(ps, u, 1.0f);
    s = t * ps;
    float pc = -1.1470746e-11f;
    pc = fmaf(pc, u, 2.0876757e-9f);
    pc = fmaf(pc, u, -2.7557319e-7f);
    pc = fmaf(pc, u, 2.4801587e-5f);
    pc = fmaf(pc, u, -1.3888889e-3f);
    pc = fmaf(pc, u, 4.1666667e-2f);
    pc = fmaf(pc, u, -0.5f);
    c = fmaf(pc, u, 1.0f);
}

__global__ void __launch_bounds__(256)
qsim_kernel(const float4* __restrict__ x4, float4* __restrict__ out4) {
    const int b = blockIdx.x;
    const int c = threadIdx.x;

    // x[b, 4c .. 4c+3]  (coalesced LDG.128)
    const float4 xv = x4[b * NC + c];
    const float4* wt = reinterpret_cast<const float4*>(g_wtrig) + c * 4;
    const float4 cw0 = wt[0];
    const float4 sw0 = wt[1];
    const float4 cw1 = wt[2];
    const float4 sw1 = wt[3];

    const float xa[4]  = {xv.x, xv.y, xv.z, xv.w};
    const float c0a[4] = {cw0.x, cw0.y, cw0.z, cw0.w};
    const float s0a[4] = {sw0.x, sw0.y, sw0.z, sw0.w};
    const float g1c[4] = {cw1.x, cw1.y, cw1.z, cw1.w};
    const float g1s[4] = {sw1.x, sw1.y, sw1.z, sw1.w};

    // Embedding merged with layer-1 RX: theta_q = (x_q + w0_q)/2 via angle addition.
    float ch[4], sh[4];
#pragma unroll
    for (int q = 0; q < 4; ++q) {
        float sx, cx;
        sincos_poly(0.5f * xa[q], sx, cx);
        ch[q] = cx * c0a[q] - sx * s0a[q];
        sh[q] = sx * c0a[q] + cx * s0a[q];
    }

    // Product-state magnitudes m[x] = prod_q (bit? sin : cos), x = b0*8+b1*4+b2*2+b3.
    float f0[2] = {ch[0], sh[0]};
    float f1[2] = {ch[1], sh[1]};
    float f2[2] = {ch[2], sh[2]};
    float f3[2] = {ch[3], sh[3]};
    float m2[4], m3[8], m4[16];
#pragma unroll
    for (int i = 0; i < 2; ++i)
#pragma unroll
        for (int j = 0; j < 2; ++j) m2[i * 2 + j] = f0[i] * f1[j];
#pragma unroll
    for (int i = 0; i < 4; ++i)
#pragma unroll
        for (int j = 0; j < 2; ++j) m3[i * 2 + j] = m2[i] * f2[j];
#pragma unroll
    for (int i = 0; i < 8; ++i)
#pragma unroll
        for (int j = 0; j < 2; ++j) m4[i * 2 + j] = m3[i] * f3[j];

    // amp(x) = (-i)^{popcount} m(x).  Convention: amp = su (real) if parity even,
    // amp = -i*su if odd, with su = m * (-1)^{floor(popcount/2)}.
    // Apply CNOT ring 1 permutation y = L(x) at the same time (compile-time).
    float su[16];
#pragma unroll
    for (int x = 0; x < 16; ++x) {
        const int b0 = (x >> 3) & 1, b1 = (x >> 2) & 1, b2 = (x >> 1) & 1, b3 = x & 1;
        const int y0 = b1 ^ b2 ^ b3;
        const int y1 = b0 ^ b1;
        const int y2 = b0 ^ b1 ^ b2;
        const int y3 = b0 ^ b1 ^ b2 ^ b3;
        const int y = y0 * 8 + y1 * 4 + y2 * 2 + y3;
        const int pcnt = b0 + b1 + b2 + b3;
        su[y] = ((pcnt >> 1) & 1) ? -m4[x] : m4[x];
    }

    // Layer-2 RX gates (commute; apply q3 first while state stays real-pure).
    // q3: pairs differ in y3 -> real Givens rotation.
    {
        const float cg = g1c[3], sg = g1s[3];
#pragma unroll
        for (int yy = 0; yy < 16; yy += 2) {
            const float v0 = su[yy], v1 = su[yy + 1];
            su[yy]     = cg * v0 - sg * v1;
            su[yy + 1] = sg * v0 + cg * v1;
        }
    }

    // q2: pairs same-purity -> state becomes complex, but sparse (1 product/component).
    float re[16], im[16];
    {
        const float cg = g1c[2], sg = g1s[2];
#pragma unroll
        for (int hi = 0; hi < 16; hi += 4) {
#pragma unroll
            for (int lo = 0; lo < 2; ++lo) {
                const int i0 = hi + lo, i1 = i0 + 2;
                const float u0 = su[i0], u1 = su[i1];
                if (lo == 0) { // y3=0: amps real u
                    re[i0] = cg * u0;  im[i0] = -sg * u1;
                    re[i1] = cg * u1;  im[i1] = -sg * u0;
                } else {       // y3=1: amps = -i*u  (re=0, im=-u)
                    re[i0] = -sg * u1; im[i0] = -cg * u0;
                    re[i1] = -sg * u0; im[i1] = -cg * u1;
                }
            }
        }
    }

    // q1: full complex RX, pairs differ in bit 4.
    {
        const float cg = g1c[1], sg = g1s[1];
#pragma unroll
        for (int hi = 0; hi < 16; hi += 8) {
#pragma unroll
            for (int lo = 0; lo < 4; ++lo) {
                const int i0 = hi + lo, i1 = i0 + 4;
                const float r0 = re[i0], i0v = im[i0], r1 = re[i1], i1v = im[i1];
                re[i0] = cg * r0 + sg * i1v;
                im[i0] = cg * i0v - sg * r1;
                re[i1] = cg * r1 + sg * i0v;
                im[i1] = cg * i1v - sg * r0;
            }
        }
    }

    // q0: full complex RX, pairs differ in bit 8.
    {
        const float cg = g1c[0], sg = g1s[0];
#pragma unroll
        for (int lo = 0; lo < 8; ++lo) {
            const int i0 = lo, i1 = lo + 8;
            const float r0 = re[i0], i0v = im[i0], r1 = re[i1], i1v = im[i1];
            re[i0] = cg * r0 + sg * i1v;
            im[i0] = cg * i0v - sg * r1;
            re[i1] = cg * r1 + sg * i0v;
            im[i1] = cg * i1v - sg * r0;
        }
    }

    // Measurement. CNOT ring 2 folded into sign masks: <Z_q> = sum_z (-1)^{(Lz)_q} |amp(z)|^2
    // (Lz)_0 = z1^z2^z3, (Lz)_1 = z0^z1, (Lz)_2 = z0^z1^z2, (Lz)_3 = z0^z1^z2^z3.
    float S[8], D[8];
#pragma unroll
    for (int j = 0; j < 8; ++j) {
        const int ya = 2 * j, yb = 2 * j + 1;
        const float pa = re[ya] * re[ya] + im[ya] * im[ya];
        const float pb = re[yb] * re[yb] + im[yb] * im[yb];
        S[j] = pa + pb;
        D[j] = pa - pb;
    }
    float o0 = 0.f, o1 = 0.f, o2 = 0.f, o3 = 0.f;
#pragma unroll
    for (int j = 0; j < 8; ++j) {
        const int z0 = (j >> 2) & 1, z1 = (j >> 1) & 1, z2 = j & 1;
        o0 += ((z1 ^ z2) ? -D[j] : D[j]);
        o1 += ((z0 ^ z1) ? -S[j] : S[j]);
        o2 += ((z0 ^ z1 ^ z2) ? -S[j] : S[j]);
        o3 += ((z0 ^ z1 ^ z2) ? -D[j] : D[j]);
    }

    float4 o;
    o.x = o0; o.y = o1; o.z = o2; o.w = o3;
    out4[b * NC + c] = o;  // out[b, 4c .. 4c+3]  (coalesced STG.128)
}

extern "C" void kernel_launch(void* const* d_in, const int* in_sizes, int n_in,
                              void* d_out, int out_size) {
    const float* x = (const float*)d_in[0];        // (4096, 1024)
    const float* w = (const float*)d_in[1];        // (256, 2, 4)
    float* out = (float*)d_out;                    // (4096, 1024)

    prep_kernel<<<1, 256>>>(w);
    qsim_kernel<<<NB, 256>>>(reinterpret_cast<const float4*>(x),
                             reinterpret_cast<float4*>(out));
}

// round 2
// speedup vs baseline: 1.0014x; 1.0014x over previous
#include <cuda_runtime.h>
#include <math.h>
#include <stdint.h>

#define NB  4096
#define NBH 2048
#define NC  256

// Per-circuit precomputed trig: [c][0..3]=cos(w0/2), [4..7]=sin(w0/2),
//                               [8..11]=cos(w1/2), [12..15]=sin(w1/2)
__device__ float g_wtrig[NC * 16];

__global__ void prep_kernel(const float* __restrict__ w) {
    int c = threadIdx.x;
    if (c >= NC) return;
#pragma unroll
    for (int l = 0; l < 2; ++l) {
#pragma unroll
        for (int q = 0; q < 4; ++q) {
            float a = 0.5f * w[c * 8 + l * 4 + q];
            float s, co;
            sincosf(a, &s, &co);
            g_wtrig[c * 16 + l * 8 + q] = co;
            g_wtrig[c * 16 + l * 8 + 4 + q] = s;
        }
    }
}

// ---------- packed f32x2 helpers (sm_100+ FFMA2 path) ----------
__device__ __forceinline__ uint64_t pk2(float a, float b) {
    uint64_t r; asm("mov.b64 %0, {%1, %2};" : "=l"(r) : "f"(a), "f"(b)); return r;
}
__device__ __forceinline__ uint64_t bc(float a) {   // broadcast scalar to both lanes
    uint64_t r; asm("mov.b64 %0, {%1, %1};" : "=l"(r) : "f"(a)); return r;
}
__device__ __forceinline__ void upk(uint64_t v, float& a, float& b) {
    asm("mov.b64 {%0, %1}, %2;" : "=f"(a), "=f"(b) : "l"(v));
}
__device__ __forceinline__ uint64_t ffma2(uint64_t a, uint64_t b, uint64_t c) {
    uint64_t r; asm("fma.rn.f32x2 %0, %1, %2, %3;" : "=l"(r) : "l"(a), "l"(b), "l"(c)); return r;
}
__device__ __forceinline__ uint64_t fmul2(uint64_t a, uint64_t b) {
    uint64_t r; asm("mul.rn.f32x2 %0, %1, %2;" : "=l"(r) : "l"(a), "l"(b)); return r;
}
__device__ __forceinline__ uint64_t fadd2(uint64_t a, uint64_t b) {
    uint64_t r; asm("add.rn.f32x2 %0, %1, %2;" : "=l"(r) : "l"(a), "l"(b)); return r;
}
__device__ __forceinline__ uint64_t fsub2(uint64_t a, uint64_t b) {
    uint64_t r; asm("sub.rn.f32x2 %0, %1, %2;" : "=l"(r) : "l"(a), "l"(b)); return r;
}

// sin/cos Taylor-Horner (|t| <= ~3.2, err < 2e-5), packed both lanes.
__device__ __forceinline__ void sincos2(uint64_t t, uint64_t& s, uint64_t& c) {
    uint64_t u = fmul2(t, t);
    uint64_t ps = bc(1.6059044e-10f);
    ps = ffma2(ps, u, bc(-2.5052108e-8f));
    ps = ffma2(ps, u, bc(2.7557319e-6f));
    ps = ffma2(ps, u, bc(-1.9841270e-4f));
    ps = ffma2(ps, u, bc(8.3333333e-3f));
    ps = ffma2(ps, u, bc(-1.6666667e-1f));
    ps = ffma2(ps, u, bc(1.0f));
    s = fmul2(t, ps);
    uint64_t pc = bc(-1.1470746e-11f);
    pc = ffma2(pc, u, bc(2.0876757e-9f));
    pc = ffma2(pc, u, bc(-2.7557319e-7f));
    pc = ffma2(pc, u, bc(2.4801587e-5f));
    pc = ffma2(pc, u, bc(-1.3888889e-3f));
    pc = ffma2(pc, u, bc(4.1666667e-2f));
    pc = ffma2(pc, u, bc(-0.5f));
    c = ffma2(pc, u, bc(1.0f));
}

// CNOT-ring-1 permutation (y = L(x)) + (-1)^{floor(popc/2)} sign, precomputed:
// SRC[y] = x with L(x)=y ; SGN[y] = sign of that amplitude's magnitude.
__device__ __constant__ const int SRC_[1] = {0}; // (unused placeholder)

__global__ void __launch_bounds__(256, 2)
qsim2_kernel(const float4* __restrict__ x4, float4* __restrict__ out4) {
    const int b = blockIdx.x;     // 0..2047 ; lanes = rows b and b+2048
    const int c = threadIdx.x;

    const float4 xva = x4[b * NC + c];
    const float4 xvb = x4[(b + NBH) * NC + c];
    const float4* wt = reinterpret_cast<const float4*>(g_wtrig) + c * 4;
    const float4 cw0 = wt[0];
    const float4 sw0 = wt[1];
    const float4 cw1 = wt[2];
    const float4 sw1 = wt[3];

    const float c0s[4] = {cw0.x, cw0.y, cw0.z, cw0.w};
    const float s0s[4] = {sw0.x, sw0.y, sw0.z, sw0.w};
    const float g1c[4] = {cw1.x, cw1.y, cw1.z, cw1.w};
    const float g1s[4] = {sw1.x, sw1.y, sw1.z, sw1.w};

    uint64_t xq[4];
    xq[0] = pk2(xva.x, xvb.x);
    xq[1] = pk2(xva.y, xvb.y);
    xq[2] = pk2(xva.z, xvb.z);
    xq[3] = pk2(xva.w, xvb.w);

    // Embedding merged with layer-1 RX via angle addition.
    uint64_t ch[4], sh[4];
    const uint64_t half = bc(0.5f);
#pragma unroll
    for (int q = 0; q < 4; ++q) {
        uint64_t t = fmul2(xq[q], half);
        uint64_t sx, cx;
        sincos2(t, sx, cx);
        const uint64_t c0p = bc(c0s[q]);
        const uint64_t s0p = bc(s0s[q]);
        const uint64_t ns0p = bc(-s0s[q]);
        ch[q] = ffma2(cx, c0p, fmul2(sx, ns0p));
        sh[q] = ffma2(sx, c0p, fmul2(cx, s0p));
    }

    // Product-state magnitudes m4[x], x = b0*8+b1*4+b2*2+b3.
    uint64_t m2[4], m3[8], m4[16];
    m2[0] = fmul2(ch[0], ch[1]); m2[1] = fmul2(ch[0], sh[1]);
    m2[2] = fmul2(sh[0], ch[1]); m2[3] = fmul2(sh[0], sh[1]);
#pragma unroll
    for (int i = 0; i < 4; ++i) {
        m3[2 * i]     = fmul2(m2[i], ch[2]);
        m3[2 * i + 1] = fmul2(m2[i], sh[2]);
    }
#pragma unroll
    for (int i = 0; i < 8; ++i) {
        m4[2 * i]     = fmul2(m3[i], ch[3]);
        m4[2 * i + 1] = fmul2(m3[i], sh[3]);
    }

    // Permutation + sign tables (compile-time, derived from ring-1 CNOTs and (-i)^popc).
    const int   SRC[16] = {0, 13, 3, 14, 6, 11, 5, 8, 12, 1, 15, 2, 10, 7, 9, 4};
    const int   SGN[16] = {+1, -1, -1, -1, -1, -1, -1, +1, -1, +1, +1, +1, -1, -1, -1, +1};

    // Layer-2 q3 RX: real Givens on pairs (e, e+1); source signs folded into coeffs.
    uint64_t su[16];
    {
        const uint64_t cp = bc(g1c[3]), ncp = bc(-g1c[3]);
        const uint64_t sp = bc(g1s[3]), nsp = bc(-g1s[3]);
#pragma unroll
        for (int e = 0; e < 16; e += 2) {
            const uint64_t m0 = m4[SRC[e]];
            const uint64_t m1 = m4[SRC[e + 1]];
            const bool p0 = SGN[e] > 0, p1 = SGN[e + 1] > 0;
            su[e]     = ffma2(m0, p0 ? cp : ncp, fmul2(m1, p1 ? nsp : sp));
            su[e + 1] = ffma2(m0, p0 ? sp : nsp, fmul2(m1, p1 ? cp : ncp));
        }
    }

    // q2 RX: state turns complex but sparse (single product per component).
    uint64_t re[16], im[16];
    {
        const uint64_t cp = bc(g1c[2]), ncp = bc(-g1c[2]);
        const uint64_t nsp = bc(-g1s[2]);
#pragma unroll
        for (int hi = 0; hi < 16; hi += 4) {
            {   // lo = 0 (y3=0: real amplitudes)
                const int i0 = hi, i1 = hi + 2;
                re[i0] = fmul2(cp, su[i0]);   im[i0] = fmul2(nsp, su[i1]);
                re[i1] = fmul2(cp, su[i1]);   im[i1] = fmul2(nsp, su[i0]);
            }
            {   // lo = 1 (y3=1: amplitudes -i*u)
                const int i0 = hi + 1, i1 = hi + 3;
                re[i0] = fmul2(nsp, su[i1]);  im[i0] = fmul2(ncp, su[i0]);
                re[i1] = fmul2(nsp, su[i0]);  im[i1] = fmul2(ncp, su[i1]);
            }
        }
    }

    // q1 RX: full complex, pairs differ in bit 4.
    {
        const uint64_t cp = bc(g1c[1]);
        const uint64_t sp = bc(g1s[1]), nsp = bc(-g1s[1]);
#pragma unroll
        for (int hi = 0; hi < 16; hi += 8) {
#pragma unroll
            for (int lo = 0; lo < 4; ++lo) {
                const int i0 = hi + lo, i1 = i0 + 4;
                const uint64_t r0 = re[i0], i0v = im[i0], r1 = re[i1], i1v = im[i1];
                re[i0] = ffma2(r0, cp, fmul2(i1v, sp));
                im[i0] = ffma2(i0v, cp, fmul2(r1, nsp));
                re[i1] = ffma2(r1, cp, fmul2(i0v, sp));
                im[i1] = ffma2(i1v, cp, fmul2(r0, nsp));
            }
        }
    }

    // q0 RX: full complex, pairs differ in bit 8.
    {
        const uint64_t cp = bc(g1c[0]);
        const uint64_t sp = bc(g1s[0]), nsp = bc(-g1s[0]);
#pragma unroll
        for (int lo = 0; lo < 8; ++lo) {
            const int i0 = lo, i1 = lo + 8;
            const uint64_t r0 = re[i0], i0v = im[i0], r1 = re[i1], i1v = im[i1];
            re[i0] = ffma2(r0, cp, fmul2(i1v, sp));
            im[i0] = ffma2(i0v, cp, fmul2(r1, nsp));
            re[i1] = ffma2(r1, cp, fmul2(i0v, sp));
            im[i1] = ffma2(i1v, cp, fmul2(r0, nsp));
        }
    }

    // Measurement; CNOT ring 2 folded into sign masks.
    uint64_t S[8], D[8];
#pragma unroll
    for (int j = 0; j < 8; ++j) {
        const int ya = 2 * j, yb = 2 * j + 1;
        const uint64_t pa = ffma2(re[ya], re[ya], fmul2(im[ya], im[ya]));
        const uint64_t pb = ffma2(re[yb], re[yb], fmul2(im[yb], im[yb]));
        S[j] = fadd2(pa, pb);
        D[j] = fsub2(pa, pb);
    }
    uint64_t o0 = bc(0.0f), o1 = o0, o2 = o0, o3 = o0;
#pragma unroll
    for (int j = 0; j < 8; ++j) {
        const int z0 = (j >> 2) & 1, z1 = (j >> 1) & 1, z2 = j & 1;
        o0 = (z1 ^ z2)      ? fsub2(o0, D[j]) : fadd2(o0, D[j]);
        o1 = (z0 ^ z1)      ? fsub2(o1, S[j]) : fadd2(o1, S[j]);
        o2 = (z0 ^ z1 ^ z2) ? fsub2(o2, S[j]) : fadd2(o2, S[j]);
        o3 = (z0 ^ z1 ^ z2) ? fsub2(o3, D[j]) : fadd2(o3, D[j]);
    }

    float a0, b0v, a1, b1v, a2, b2v, a3, b3v;
    upk(o0, a0, b0v); upk(o1, a1, b1v); upk(o2, a2, b2v); upk(o3, a3, b3v);

    float4 oa, ob;
    oa.x = a0;  oa.y = a1;  oa.z = a2;  oa.w = a3;
    ob.x = b0v; ob.y = b1v; ob.z = b2v; ob.w = b3v;
    out4[b * NC + c] = oa;              // row b        (coalesced STG.128)
    out4[(b + NBH) * NC + c] = ob;      // row b+2048   (coalesced STG.128)
}

extern "C" void kernel_launch(void* const* d_in, const int* in_sizes, int n_in,
                              void* d_out, int out_size) {
    const float* x = (const float*)d_in[0];        // (4096, 1024)
    const float* w = (const float*)d_in[1];        // (256, 2, 4)
    float* out = (float*)d_out;                    // (4096, 1024)

    prep_kernel<<<1, 256>>>(w);
    qsim2_kernel<<<NBH, 256>>>(reinterpret_cast<const float4*>(x),
                               reinterpret_cast<float4*>(out));
}

// round 4
// speedup vs baseline: 1.5230x; 1.5209x over previous
#include <cuda_runtime.h>
#include <math.h>

#define NB 4096
#define NC 256

// Per-circuit constants: [0..3]=cos(w0_q), [4..7]=sin(w0_q),
// [8..19] = A0,B0,E0,F0, A1,B1,A2,B2, A3,B3,E3,F3   (20 floats)
__device__ float g_coef[NC * 20];

// ---- Exact 4-qubit sim (verified R1 path), parameterized by half-angle trig ----
__device__ void sim_probe(const float ch[4], const float sh[4],
                          const float g1c[4], const float g1s[4], float o[4]) {
    float f0[2] = {ch[0], sh[0]};
    float f1[2] = {ch[1], sh[1]};
    float f2[2] = {ch[2], sh[2]};
    float f3[2] = {ch[3], sh[3]};
    float m2[4], m3[8], m4[16];
    for (int i = 0; i < 2; ++i)
        for (int j = 0; j < 2; ++j) m2[i * 2 + j] = f0[i] * f1[j];
    for (int i = 0; i < 4; ++i)
        for (int j = 0; j < 2; ++j) m3[i * 2 + j] = m2[i] * f2[j];
    for (int i = 0; i < 8; ++i)
        for (int j = 0; j < 2; ++j) m4[i * 2 + j] = m3[i] * f3[j];

    float su[16];
    for (int x = 0; x < 16; ++x) {
        const int b0 = (x >> 3) & 1, b1 = (x >> 2) & 1, b2 = (x >> 1) & 1, b3 = x & 1;
        const int y = (b1 ^ b2 ^ b3) * 8 + (b0 ^ b1) * 4 + (b0 ^ b1 ^ b2) * 2 + (b0 ^ b1 ^ b2 ^ b3);
        const int pcnt = b0 + b1 + b2 + b3;
        su[y] = ((pcnt >> 1) & 1) ? -m4[x] : m4[x];
    }
    {   // q3 RX (real Givens)
        const float cg = g1c[3], sg = g1s[3];
        for (int yy = 0; yy < 16; yy += 2) {
            const float v0 = su[yy], v1 = su[yy + 1];
            su[yy] = cg * v0 - sg * v1;
            su[yy + 1] = sg * v0 + cg * v1;
        }
    }
    float re[16], im[16];
    {   // q2 RX (sparse complexification)
        const float cg = g1c[2], sg = g1s[2];
        for (int hi = 0; hi < 16; hi += 4) {
            int i0 = hi, i1 = hi + 2;
            re[i0] = cg * su[i0];   im[i0] = -sg * su[i1];
            re[i1] = cg * su[i1];   im[i1] = -sg * su[i0];
            i0 = hi + 1; i1 = hi + 3;
            re[i0] = -sg * su[i1];  im[i0] = -cg * su[i0];
            re[i1] = -sg * su[i0];  im[i1] = -cg * su[i1];
        }
    }
    {   // q1 RX
        const float cg = g1c[1], sg = g1s[1];
        for (int hi = 0; hi < 16; hi += 8)
            for (int lo = 0; lo < 4; ++lo) {
                const int i0 = hi + lo, i1 = i0 + 4;
                const float r0 = re[i0], iv0 = im[i0], r1 = re[i1], iv1 = im[i1];
                re[i0] = cg * r0 + sg * iv1;
                im[i0] = cg * iv0 - sg * r1;
                re[i1] = cg * r1 + sg * iv0;
                im[i1] = cg * iv1 - sg * r0;
            }
    }
    {   // q0 RX
        const float cg = g1c[0], sg = g1s[0];
        for (int lo = 0; lo < 8; ++lo) {
            const int i0 = lo, i1 = lo + 8;
            const float r0 = re[i0], iv0 = im[i0], r1 = re[i1], iv1 = im[i1];
            re[i0] = cg * r0 + sg * iv1;
            im[i0] = cg * iv0 - sg * r1;
            re[i1] = cg * r1 + sg * iv0;
            im[i1] = cg * iv1 - sg * r0;
        }
    }
    float S[8], D[8];
    for (int j = 0; j < 8; ++j) {
        const int ya = 2 * j, yb = 2 * j + 1;
        const float pa = re[ya] * re[ya] + im[ya] * im[ya];
        const float pb = re[yb] * re[yb] + im[yb] * im[yb];
        S[j] = pa + pb;
        D[j] = pa - pb;
    }
    float o0 = 0.f, o1 = 0.f, o2 = 0.f, o3 = 0.f;
    for (int j = 0; j < 8; ++j) {
        const int z0 = (j >> 2) & 1, z1 = (j >> 1) & 1, z2 = j & 1;
        o0 += ((z1 ^ z2) ? -D[j] : D[j]);
        o1 += ((z0 ^ z1) ? -S[j] : S[j]);
        o2 += ((z0 ^ z1 ^ z2) ? -S[j] : S[j]);
        o3 += ((z0 ^ z1 ^ z2) ? -D[j] : D[j]);
    }
    o[0] = o0; o[1] = o1; o[2] = o2; o[3] = o3;
}

// Prep: 6 blocks (one per probe point), 256 threads (one per circuit).
// Probe masks: bit q set -> Theta_q = pi/2 (half-angle pi/4), else Theta_q = 0.
//   p0=0x0 -> A0,A1,A2,A3      p1=0xB -> B0
//   p2=0xA -> E0,B2            p3=0x1 -> F0,F3
//   p4=0x5 -> B1,B3            p5=0x4 -> E3
__global__ void prep_kernel(const float* __restrict__ w) {
    const int c = threadIdx.x;
    const int p = blockIdx.x;
    if (c >= NC) return;

    float g1c[4], g1s[4];
#pragma unroll
    for (int q = 0; q < 4; ++q) {
        float s, co;
        sincosf(0.5f * w[c * 8 + 4 + q], &s, &co);   // half angle w1
        g1c[q] = co; g1s[q] = s;
    }

    const int pm[6] = {0x0, 0xB, 0xA, 0x1, 0x5, 0x4};
    const float R = 0.70710678118654752f;
    float ch[4], sh[4];
#pragma unroll
    for (int q = 0; q < 4; ++q) {
        const bool hot = (pm[p] >> q) & 1;
        ch[q] = hot ? R : 1.0f;
        sh[q] = hot ? R : 0.0f;
    }
    float O[4];
    sim_probe(ch, sh, g1c, g1s, O);

    float* P = g_coef + c * 20;
    switch (p) {
        case 0:
#pragma unroll
            for (int q = 0; q < 4; ++q) {     // also write w0 trig once
                float s, co;
                sincosf(w[c * 8 + q], &s, &co);
                P[q] = co; P[4 + q] = s;
            }
            P[8]  = O[0];   // A0
            P[12] = O[1];   // A1
            P[14] = O[2];   // A2
            P[16] = O[3];   // A3
            break;
        case 1: P[9]  = O[0]; break;              // B0
        case 2: P[10] = O[0]; P[15] = O[2]; break; // E0, B2
        case 3: P[11] = O[0]; P[19] = O[3]; break; // F0, F3
        case 4: P[13] = O[1]; P[17] = O[3]; break; // B1, B3
        case 5: P[18] = O[3]; break;               // E3
    }
}

// sin(t), cos(t) Taylor-Horner, |t| <= ~3.2, err < 2e-5. FMA pipe only.
__device__ __forceinline__ void sincos_poly(float t, float& s, float& c) {
    float u = t * t;
    float ps = 1.6059044e-10f;
    ps = fmaf(ps, u, -2.5052108e-8f);
    ps = fmaf(ps, u, 2.7557319e-6f);
    ps = fmaf(ps, u, -1.9841270e-4f);
    ps = fmaf(ps, u, 8.3333333e-3f);
    ps = fmaf(ps, u, -1.6666667e-1f);
    ps = fmaf(ps, u, 1.0f);
    s = t * ps;
    float pc = -1.1470746e-11f;
    pc = fmaf(pc, u, 2.0876757e-9f);
    pc = fmaf(pc, u, -2.7557319e-7f);
    pc = fmaf(pc, u, 2.4801587e-5f);
    pc = fmaf(pc, u, -1.3888889e-3f);
    pc = fmaf(pc, u, 4.1666667e-2f);
    pc = fmaf(pc, u, -0.5f);
    c = fmaf(pc, u, 1.0f);
}

__global__ void __launch_bounds__(256)
qsim3_kernel(const float4* __restrict__ x4, float4* __restrict__ out4) {
    const int b = blockIdx.x;
    const int c = threadIdx.x;

    const float4 xv = x4[b * NC + c];
    const float* P = g_coef + c * 20;
    const float4 kc = *reinterpret_cast<const float4*>(P);       // cos(w0)
    const float4 ks = *reinterpret_cast<const float4*>(P + 4);   // sin(w0)
    const float4 k2 = *reinterpret_cast<const float4*>(P + 8);   // A0,B0,E0,F0
    const float4 k3 = *reinterpret_cast<const float4*>(P + 12);  // A1,B1,A2,B2
    const float4 k4 = *reinterpret_cast<const float4*>(P + 16);  // A3,B3,E3,F3

    const float xa[4]  = {xv.x, xv.y, xv.z, xv.w};
    const float cwa[4] = {kc.x, kc.y, kc.z, kc.w};
    const float swa[4] = {ks.x, ks.y, ks.z, ks.w};

    // Full-angle trig of Theta_q = x_q + w0_q via half-angle poly + double + rotate.
    float C[4], S[4];
#pragma unroll
    for (int q = 0; q < 4; ++q) {
        float sh, ch;
        sincos_poly(0.5f * xa[q], sh, ch);
        const float sh2 = sh * sh;
        const float cx = fmaf(sh2, -2.0f, 1.0f);   // cos x
        const float shch = sh * ch;
        const float sx = shch + shch;              // sin x
        C[q] = fmaf(cx, cwa[q], -(sx * swa[q]));   // cos(x+w0)
        S[q] = fmaf(sx, cwa[q],  (cx * swa[q]));   // sin(x+w0)
    }

    // Shared monomials
    const float C1C3 = C[1] * C[3];
    const float S1S3 = S[1] * S[3];
    const float C0C2 = C[0] * C[2];
    const float S0S2 = S[0] * S[2];
    const float C0S2 = C[0] * S[2];
    const float S0C2 = S[0] * C[2];

    // <Z0> = A0*C0C1C3 + B0*S0S1S3 + E0*C0S1S3 + F0*S0C1C3
    float o0 = k2.x * (C[0] * C1C3);
    o0 = fmaf(k2.y, S[0] * S1S3, o0);
    o0 = fmaf(k2.z, C[0] * S1S3, o0);
    o0 = fmaf(k2.w, S[0] * C1C3, o0);

    // <Z1> = A1*C0C2C3 + B1*S0S2C3
    float o1 = k3.x * (C0C2 * C[3]);
    o1 = fmaf(k3.y, S0S2 * C[3], o1);

    // <Z2> = A2*C1C3 + B2*S1S3
    float o2 = fmaf(k3.z, C1C3, k3.w * S1S3);

    // <Z3> = A3*C0C2 + B3*S0S2 + E3*C0S2 + F3*S0C2
    float o3 = k4.x * C0C2;
    o3 = fmaf(k4.y, S0S2, o3);
    o3 = fmaf(k4.z, C0S2, o3);
    o3 = fmaf(k4.w, S0C2, o3);

    float4 o;
    o.x = o0; o.y = o1; o.z = o2; o.w = o3;
    out4[b * NC + c] = o;
}

extern "C" void kernel_launch(void* const* d_in, const int* in_sizes, int n_in,
                              void* d_out, int out_size) {
    const float* x = (const float*)d_in[0];        // (4096, 1024)
    const float* w = (const float*)d_in[1];        // (256, 2, 4)
    float* out = (float*)d_out;                    // (4096, 1024)

    prep_kernel<<<6, 256>>>(w);
    qsim3_kernel<<<NB, 256>>>(reinterpret_cast<const float4*>(x),
                              reinterpret_cast<float4*>(out));
}